// round 10
// baseline (speedup 1.0000x reference)
#include <cuda_runtime.h>
#include <cuda_bf16.h>

// NCELoss: N=4096, E=1024, K=50 noise (+1 target), V=50257. Scalar f32 loss.
//
// R1-R9 established the binding wall: 856 MB of weight traffic through LTS
// (L2->L1) at its ~10 TB/s practical ceiling, invariant across designs.
// This version reduces LTS bytes instead of rearranging them:
//   A: convert input to bf16 (8 MB) + zero per-row counters
//   B: scatter all N*51 samples into per-weight-row buckets (atomic slots)
//   C: MAIN - one warp per weight row: load the fp32 row into registers ONCE
//      (weight LTS 856 -> 203 MB), then dot against each bucketed sample's
//      bf16 input row (input LTS 428 MB). Logit (+bias) scattered to g_logit.
//   D: loss pass: per-example terms from g_logit + ticket reduce -> out.
// Bucket fill order is atomic-racy but each logit is computed independently
// from the same data -> output is bit-deterministic. All counters reset
// every call (graph-replay safe). No allocations: static __device__ scratch.

#define EDIM    1024
#define KNOISE  50
#define NCOLS   (KNOISE + 1)
#define NORM_TERM 9.0f
#define VMAX    50260
#define NMAX    4096
#define CAP     64            // bucket capacity (Poisson mean 4.16 -> safe)

__device__ __nv_bfloat16 g_xbf[NMAX * EDIM];       // 8.4 MB bf16 input
__device__ int           g_cnt[VMAX];              // per-row sample counts
__device__ int           g_bucket[VMAX * CAP];     // entries: n*51+j
__device__ float         g_logit[NMAX * NCOLS];    // logit incl. bias
__device__ double        g_cpart[64];
__device__ unsigned int  g_done = 0;

// ---------------- A: zero counters + convert input to bf16 ----------------
__global__ void prep_kernel(const float* __restrict__ input, int N, int V)
{
    const int tid    = blockIdx.x * blockDim.x + threadIdx.x;
    const int stride = gridDim.x * blockDim.x;

    for (int i = tid; i < V; i += stride) g_cnt[i] = 0;

    const int npairs = N * EDIM / 2;
    const float2* in2 = reinterpret_cast<const float2*>(input);
    __nv_bfloat162* ob = reinterpret_cast<__nv_bfloat162*>(g_xbf);
    for (int i = tid; i < npairs; i += stride)
        ob[i] = __float22bfloat162_rn(in2[i]);
}

// ---------------- B: scatter samples into per-row buckets -----------------
__global__ void scatter_kernel(const int* __restrict__ target,
                               const int* __restrict__ noise_samples,
                               int N)
{
    const int i = blockIdx.x * blockDim.x + threadIdx.x;
    if (i >= N * NCOLS) return;
    const int n = i / NCOLS;
    const int j = i - n * NCOLS;
    const int idx = (j == 0) ? __ldg(&target[n])
                             : __ldg(&noise_samples[n * KNOISE + (j - 1)]);
    const int slot = atomicAdd(&g_cnt[idx], 1);
    if (slot < CAP) g_bucket[idx * CAP + slot] = i;   // entry = n*NCOLS+j
}

// ---------------- C: main - warp per weight row ----------------------------
__global__ __launch_bounds__(256) void dot_kernel(
    const float* __restrict__ weight,
    const float* __restrict__ bias,
    int V)
{
    const int lane   = threadIdx.x & 31;
    const int warpg  = (blockIdx.x * blockDim.x + threadIdx.x) >> 5;
    const int nwarps = (gridDim.x * blockDim.x) >> 5;

    for (int r = warpg; r < V; r += nwarps) {
        int c = __ldg(&g_cnt[r]);
        if (c == 0) continue;
        if (c > CAP) c = CAP;

        // Load the full 4 KB weight row into registers (once per row).
        const float4* w4 = reinterpret_cast<const float4*>(
            weight + (size_t)r * EDIM);
        float4 wr[8];
        #pragma unroll
        for (int i = 0; i < 8; i++) wr[i] = __ldg(&w4[lane + 32 * i]);

        const float brow = __ldg(&bias[r]);

        for (int s = 0; s < c; s++) {
            const int e = __ldg(&g_bucket[r * CAP + s]);
            const int n = e / NCOLS;

            // bf16 input row: 8 x LDG.64 per lane (4 bf16 each), matching
            // the weight float4 element layout exactly.
            const uint2* xp = reinterpret_cast<const uint2*>(
                g_xbf + (size_t)n * EDIM);
            uint2 xr[8];
            #pragma unroll
            for (int i = 0; i < 8; i++) xr[i] = __ldg(&xp[lane + 32 * i]);

            float d = 0.0f;
            #pragma unroll
            for (int i = 0; i < 8; i++) {
                const __nv_bfloat162 lo = *reinterpret_cast<const __nv_bfloat162*>(&xr[i].x);
                const __nv_bfloat162 hi = *reinterpret_cast<const __nv_bfloat162*>(&xr[i].y);
                const float2 a = __bfloat1622float2(lo);
                const float2 b = __bfloat1622float2(hi);
                d += wr[i].x * a.x + wr[i].y * a.y
                   + wr[i].z * b.x + wr[i].w * b.y;
            }
            #pragma unroll
            for (int o = 16; o; o >>= 1) d += __shfl_xor_sync(0xffffffffu, d, o);

            if (lane == 0) g_logit[e] = d + brow;
        }
    }
}

// ---------------- D: loss terms + deterministic reduction ------------------
__global__ __launch_bounds__(256) void loss_kernel(
    const int*   __restrict__ target,
    const int*   __restrict__ noise_samples,
    const float* __restrict__ noise,
    float*       __restrict__ out,
    int N)
{
    __shared__ double s_dsum[8];
    __shared__ bool   s_is_last;

    const int tid  = threadIdx.x;
    const int lane = tid & 31;
    const int wid  = tid >> 5;
    const int n    = blockIdx.x * blockDim.x + tid;

    float acc = 0.0f;
    if (n < N) {
        #pragma unroll 1
        for (int j = 0; j < NCOLS; j++) {
            const int idx = (j == 0) ? __ldg(&target[n])
                                     : __ldg(&noise_samples[n * KNOISE + (j - 1)]);
            const float l  = g_logit[n * NCOLS + j];
            const float p  = expf(l - NORM_TERM);
            const float kp = (float)KNOISE * __ldg(&noise[idx]);
            const float num = (j == 0) ? p : kp;
            acc += logf(num / (p + kp));
        }
    }

    // Block reduce (double).
    double d = (double)acc;
    #pragma unroll
    for (int o = 16; o; o >>= 1) d += __shfl_xor_sync(0xffffffffu, d, o);
    if (lane == 0) s_dsum[wid] = d;
    __syncthreads();
    if (wid == 0) {
        double t = (lane < 8) ? s_dsum[lane] : 0.0;
        #pragma unroll
        for (int o = 4; o; o >>= 1) t += __shfl_xor_sync(0xffffffffu, t, o);
        if (lane == 0) g_cpart[blockIdx.x] = t;
    }

    if (tid == 0) {
        __threadfence();
        unsigned int prev = atomicAdd(&g_done, 1u);
        s_is_last = (prev == gridDim.x - 1);
    }
    __syncthreads();

    if (s_is_last && wid == 0) {
        double t = 0.0;
        if (lane < (int)gridDim.x) {
            asm volatile("ld.global.cg.f64 %0, [%1];"
                         : "=d"(t) : "l"(g_cpart + lane));
        }
        #pragma unroll
        for (int o = 16; o; o >>= 1) t += __shfl_xor_sync(0xffffffffu, t, o);
        if (lane == 0) {
            out[0] = (float)(-t / (double)N);
            g_done = 0u;                      // reset for graph replay
        }
    }
}

extern "C" void kernel_launch(void* const* d_in, const int* in_sizes, int n_in,
                              void* d_out, int out_size) {
    const float* input         = (const float*)d_in[0];
    const int*   target        = (const int*)  d_in[1];
    const int*   noise_samples = (const int*)  d_in[2];
    const float* noise         = (const float*)d_in[3];
    const float* weight        = (const float*)d_in[4];
    const float* bias          = (const float*)d_in[5];
    float* out = (float*)d_out;

    const int N = in_sizes[1];   // examples
    const int V = in_sizes[3];   // vocab size

    prep_kernel<<<2048, 256>>>(input, N, V);
    scatter_kernel<<<(N * NCOLS + 255) / 256, 256>>>(target, noise_samples, N);
    dot_kernel<<<888, 256>>>(weight, bias, V);
    loss_kernel<<<(N + 255) / 256, 256>>>(target, noise_samples, noise, out, N);
}

// round 11
// speedup vs baseline: 1.1770x; 1.1770x over previous
#include <cuda_runtime.h>
#include <cuda_bf16.h>

// NCELoss: N=4096, E=1024, K=50 noise (+1 target), V=50257. Scalar f32 loss.
//
// Validated model (R10): runtime = LTS bytes / ~10 TB/s. Inverted (bucketed)
// access dedupes the weight stream: 203 MB weights (once per unique row, held
// in registers) + 428 MB bf16 input (2 KB per sample) ~= 631 MB -> ~65 us.
// R10's 38.7 us serial loss pass is eliminated: the loss TERM is computed in
// dot_kernel (lane 0 already holds the logit; noise/bias are per-row loads),
// leaving only a fixed-order 209k-float sum (~3 us).
// Pipeline: prep (zero cnts + fp32->bf16 input) -> scatter (bucket samples)
// -> dot (warp per row: row in regs, term per sample) -> sum (deterministic).
// Bucket slot order is atomic-racy but each term is computed independently
// and written once -> output bit-deterministic. Graph-replay safe (counters
// reset each call). No allocations: static __device__ scratch.

#define EDIM    1024
#define KNOISE  50
#define NCOLS   (KNOISE + 1)
#define NORM_TERM 9.0f
#define VMAX    50260
#define NMAX    4096
#define CAP     64            // bucket capacity (Poisson mean 4.16 -> safe)
#define SUMBLOCKS 64

__device__ __nv_bfloat16 g_xbf[NMAX * EDIM];       // 8.4 MB bf16 input
__device__ int           g_cnt[VMAX];              // per-row sample counts
__device__ int           g_bucket[VMAX * CAP];     // entries: n*51+j
__device__ float         g_term[NMAX * NCOLS];     // per-sample loss terms
__device__ double        g_cpart[SUMBLOCKS];
__device__ unsigned int  g_done = 0;

// ---------------- A: zero counters + convert input to bf16 ----------------
__global__ void prep_kernel(const float* __restrict__ input, int N, int V)
{
    const int tid    = blockIdx.x * blockDim.x + threadIdx.x;
    const int stride = gridDim.x * blockDim.x;

    for (int i = tid; i < V; i += stride) g_cnt[i] = 0;

    const int npairs = N * EDIM / 2;
    const float2* in2 = reinterpret_cast<const float2*>(input);
    __nv_bfloat162* ob = reinterpret_cast<__nv_bfloat162*>(g_xbf);
    for (int i = tid; i < npairs; i += stride)
        ob[i] = __float22bfloat162_rn(in2[i]);
}

// ---------------- B: scatter samples into per-row buckets -----------------
__global__ void scatter_kernel(const int* __restrict__ target,
                               const int* __restrict__ noise_samples,
                               int N)
{
    const int i = blockIdx.x * blockDim.x + threadIdx.x;
    if (i >= N * NCOLS) return;
    const int n = i / NCOLS;
    const int j = i - n * NCOLS;
    const int idx = (j == 0) ? __ldg(&target[n])
                             : __ldg(&noise_samples[n * KNOISE + (j - 1)]);
    const int slot = atomicAdd(&g_cnt[idx], 1);
    if (slot < CAP) g_bucket[idx * CAP + slot] = i;   // entry = n*NCOLS+j
}

// ---------------- C: main - warp per weight row, term per sample -----------
__global__ __launch_bounds__(256) void dot_kernel(
    const float* __restrict__ weight,
    const float* __restrict__ bias,
    const float* __restrict__ noise,
    int V)
{
    const int lane   = threadIdx.x & 31;
    const int warpg  = (blockIdx.x * blockDim.x + threadIdx.x) >> 5;
    const int nwarps = (gridDim.x * blockDim.x) >> 5;

    for (int r = warpg; r < V; r += nwarps) {
        int c = __ldg(&g_cnt[r]);
        if (c == 0) continue;
        if (c > CAP) c = CAP;

        // Load the full 4 KB weight row into registers (once per row).
        const float4* w4 = reinterpret_cast<const float4*>(
            weight + (size_t)r * EDIM);
        float4 wr[8];
        #pragma unroll
        for (int i = 0; i < 8; i++) wr[i] = __ldg(&w4[lane + 32 * i]);

        const float brow = __ldg(&bias[r]);
        const float kp   = (float)KNOISE * __ldg(&noise[r]);

        for (int s = 0; s < c; s++) {
            const int e = __ldg(&g_bucket[r * CAP + s]);
            const int n = e / NCOLS;

            // bf16 input row: 8 x LDG.64 per lane, matching weight layout.
            const uint2* xp = reinterpret_cast<const uint2*>(
                g_xbf + (size_t)n * EDIM);
            uint2 xr[8];
            #pragma unroll
            for (int i = 0; i < 8; i++) xr[i] = __ldg(&xp[lane + 32 * i]);

            float d = 0.0f;
            #pragma unroll
            for (int i = 0; i < 8; i++) {
                const __nv_bfloat162 lo = *reinterpret_cast<const __nv_bfloat162*>(&xr[i].x);
                const __nv_bfloat162 hi = *reinterpret_cast<const __nv_bfloat162*>(&xr[i].y);
                const float2 a = __bfloat1622float2(lo);
                const float2 b = __bfloat1622float2(hi);
                d += wr[i].x * a.x + wr[i].y * a.y
                   + wr[i].z * b.x + wr[i].w * b.y;
            }
            #pragma unroll
            for (int o = 16; o; o >>= 1) d += __shfl_xor_sync(0xffffffffu, d, o);

            if (lane == 0) {
                const float p   = expf(d + brow - NORM_TERM);
                const bool  isT = (e - n * NCOLS) == 0;     // j == 0
                const float num = isT ? p : kp;
                g_term[e] = logf(num / (p + kp));
            }
        }
    }
}

// ---------------- D: fixed-order deterministic sum -------------------------
__global__ __launch_bounds__(256) void sum_kernel(float* __restrict__ out, int N)
{
    __shared__ double s_dsum[8];
    __shared__ bool   s_is_last;

    const int tid    = threadIdx.x;
    const int lane   = tid & 31;
    const int wid    = tid >> 5;
    const int gid    = blockIdx.x * blockDim.x + tid;
    const int stride = gridDim.x * blockDim.x;
    const int total  = N * NCOLS;

    double d = 0.0;
    for (int i = gid; i < total; i += stride) d += (double)g_term[i];

    #pragma unroll
    for (int o = 16; o; o >>= 1) d += __shfl_xor_sync(0xffffffffu, d, o);
    if (lane == 0) s_dsum[wid] = d;
    __syncthreads();
    if (wid == 0) {
        double t = (lane < 8) ? s_dsum[lane] : 0.0;
        #pragma unroll
        for (int o = 4; o; o >>= 1) t += __shfl_xor_sync(0xffffffffu, t, o);
        if (lane == 0) g_cpart[blockIdx.x] = t;
    }

    if (tid == 0) {
        __threadfence();
        unsigned int prev = atomicAdd(&g_done, 1u);
        s_is_last = (prev == gridDim.x - 1);
    }
    __syncthreads();

    if (s_is_last && wid == 0) {
        double t = 0.0;
        #pragma unroll
        for (int k = lane; k < SUMBLOCKS; k += 32) {
            double v;
            asm volatile("ld.global.cg.f64 %0, [%1];"
                         : "=d"(v) : "l"(g_cpart + k));
            t += v;
        }
        #pragma unroll
        for (int o = 16; o; o >>= 1) t += __shfl_xor_sync(0xffffffffu, t, o);
        if (lane == 0) {
            out[0] = (float)(-t / (double)N);
            g_done = 0u;                      // reset for graph replay
        }
    }
}

extern "C" void kernel_launch(void* const* d_in, const int* in_sizes, int n_in,
                              void* d_out, int out_size) {
    const float* input         = (const float*)d_in[0];
    const int*   target        = (const int*)  d_in[1];
    const int*   noise_samples = (const int*)  d_in[2];
    const float* noise         = (const float*)d_in[3];
    const float* weight        = (const float*)d_in[4];
    const float* bias          = (const float*)d_in[5];
    float* out = (float*)d_out;

    const int N = in_sizes[1];   // examples
    const int V = in_sizes[3];   // vocab size

    prep_kernel<<<1024, 256>>>(input, N, V);
    scatter_kernel<<<(N * NCOLS + 255) / 256, 256>>>(target, noise_samples, N);
    dot_kernel<<<888, 256>>>(weight, bias, noise, V);
    sum_kernel<<<SUMBLOCKS, 256>>>(out, N);
}

// round 12
// speedup vs baseline: 1.1877x; 1.0090x over previous
#include <cuda_runtime.h>
#include <cuda_bf16.h>

// NCELoss: N=4096, E=1024, K=50 noise (+1 target), V=50257. Scalar f32 loss.
//
// Validated model: runtime ~= LTS bytes / ~10 TB/s. Inverted (bucketed)
// access dedupes the weight stream: 203 MB fp32 weights (read once per
// unique row, held in registers) + 428 MB bf16 input (2 KB per sample)
// ~= 631 MB -> ~65-70 us for the dot pass.
// R11 -> R12: the per-sample loss terms are REDUCED IN-KERNEL (warp-local
// float acc -> block double -> atomicAdd; last-block ticket writes the
// scalar and resets state). This removes the 9.8 us sum pass, the g_term
// round-trip, and one launch. Sum order varies run-to-run only at the
// double-accumulation level (~ulp); rel_err stays ~6e-7 << 1e-3.
// Pipeline: prep (zero cnts + fp32->bf16 input) -> scatter (bucket samples)
// -> dot (warp per row; loss term + full reduction + output). Graph-replay
// safe: all counters reset each call. No allocations (static scratch).

#define EDIM    1024
#define KNOISE  50
#define NCOLS   (KNOISE + 1)
#define NORM_TERM 9.0f
#define VMAX    50260
#define NMAX    4096
#define CAP     64            // bucket capacity (Poisson mean 4.16 -> safe)
#define DOT_BLOCKS 888
#define DOT_WARPS  8

__device__ __nv_bfloat16 g_xbf[NMAX * EDIM];       // 8.4 MB bf16 input
__device__ int           g_cnt[VMAX];              // per-row sample counts
__device__ int           g_bucket[VMAX * CAP];     // entries: n*51+j
__device__ double        g_acc  = 0.0;             // global loss accumulator
__device__ unsigned int  g_done = 0;               // completion ticket

// ---------------- A: zero counters + convert input to bf16 ----------------
__global__ void prep_kernel(const float* __restrict__ input, int N, int V)
{
    const int tid    = blockIdx.x * blockDim.x + threadIdx.x;
    const int stride = gridDim.x * blockDim.x;

    for (int i = tid; i < V; i += stride) g_cnt[i] = 0;

    const int npairs = N * EDIM / 2;
    const float2* in2 = reinterpret_cast<const float2*>(input);
    __nv_bfloat162* ob = reinterpret_cast<__nv_bfloat162*>(g_xbf);
    for (int i = tid; i < npairs; i += stride)
        ob[i] = __float22bfloat162_rn(in2[i]);
}

// ---------------- B: scatter samples into per-row buckets -----------------
__global__ void scatter_kernel(const int* __restrict__ target,
                               const int* __restrict__ noise_samples,
                               int N)
{
    const int i = blockIdx.x * blockDim.x + threadIdx.x;
    if (i >= N * NCOLS) return;
    const int n = i / NCOLS;
    const int j = i - n * NCOLS;
    const int idx = (j == 0) ? __ldg(&target[n])
                             : __ldg(&noise_samples[n * KNOISE + (j - 1)]);
    const int slot = atomicAdd(&g_cnt[idx], 1);
    if (slot < CAP) g_bucket[idx * CAP + slot] = i;   // entry = n*NCOLS+j
}

// ------- C: main - warp per weight row, loss terms, full reduction --------
__global__ __launch_bounds__(DOT_WARPS * 32) void dot_kernel(
    const float* __restrict__ weight,
    const float* __restrict__ bias,
    const float* __restrict__ noise,
    float*       __restrict__ out,
    int V, int N)
{
    __shared__ double s_dsum[DOT_WARPS];
    __shared__ bool   s_is_last;

    const int lane   = threadIdx.x & 31;
    const int wid    = threadIdx.x >> 5;
    const int warpg  = (blockIdx.x * blockDim.x + threadIdx.x) >> 5;
    const int nwarps = (gridDim.x * blockDim.x) >> 5;

    float acc = 0.0f;                       // lane-0 loss accumulator

    for (int r = warpg; r < V; r += nwarps) {
        int c = __ldg(&g_cnt[r]);
        if (c == 0) continue;
        if (c > CAP) c = CAP;

        // Load the full 4 KB weight row into registers (once per row).
        const float4* w4 = reinterpret_cast<const float4*>(
            weight + (size_t)r * EDIM);
        float4 wr[8];
        #pragma unroll
        for (int i = 0; i < 8; i++) wr[i] = __ldg(&w4[lane + 32 * i]);

        const float brow = __ldg(&bias[r]);
        const float kp   = (float)KNOISE * __ldg(&noise[r]);

        for (int s = 0; s < c; s++) {
            const int e = __ldg(&g_bucket[r * CAP + s]);
            const int n = e / NCOLS;

            // bf16 input row: 8 x LDG.64 per lane, matching weight layout.
            const uint2* xp = reinterpret_cast<const uint2*>(
                g_xbf + (size_t)n * EDIM);
            uint2 xr[8];
            #pragma unroll
            for (int i = 0; i < 8; i++) xr[i] = __ldg(&xp[lane + 32 * i]);

            float d = 0.0f;
            #pragma unroll
            for (int i = 0; i < 8; i++) {
                const __nv_bfloat162 lo = *reinterpret_cast<const __nv_bfloat162*>(&xr[i].x);
                const __nv_bfloat162 hi = *reinterpret_cast<const __nv_bfloat162*>(&xr[i].y);
                const float2 a = __bfloat1622float2(lo);
                const float2 b = __bfloat1622float2(hi);
                d += wr[i].x * a.x + wr[i].y * a.y
                   + wr[i].z * b.x + wr[i].w * b.y;
            }
            #pragma unroll
            for (int o = 16; o; o >>= 1) d += __shfl_xor_sync(0xffffffffu, d, o);

            if (lane == 0) {
                const float p   = expf(d + brow - NORM_TERM);
                const bool  isT = (e - n * NCOLS) == 0;     // j == 0
                const float num = isT ? p : kp;
                acc += logf(num / (p + kp));
            }
        }
    }

    // Block reduction (lane 0s hold partial sums) -> global atomic.
    if (lane == 0) s_dsum[wid] = (double)acc;
    __syncthreads();
    if (wid == 0) {
        double t = (lane < DOT_WARPS) ? s_dsum[lane] : 0.0;
        #pragma unroll
        for (int o = DOT_WARPS / 2; o; o >>= 1)
            t += __shfl_xor_sync(0xffffffffu, t, o);
        if (lane == 0) atomicAdd(&g_acc, t);
    }

    // Completion ticket: last block writes the scalar and resets state.
    if (threadIdx.x == 0) {
        __threadfence();
        unsigned int prev = atomicAdd(&g_done, 1u);
        s_is_last = (prev == gridDim.x - 1);
    }
    __syncthreads();

    if (s_is_last && threadIdx.x == 0) {
        double t;
        asm volatile("ld.global.cg.f64 %0, [%1];" : "=d"(t) : "l"(&g_acc));
        out[0] = (float)(-t / (double)N);
        g_acc  = 0.0;                       // reset for graph replay
        __threadfence();
        g_done = 0u;
    }
}

extern "C" void kernel_launch(void* const* d_in, const int* in_sizes, int n_in,
                              void* d_out, int out_size) {
    const float* input         = (const float*)d_in[0];
    const int*   target        = (const int*)  d_in[1];
    const int*   noise_samples = (const int*)  d_in[2];
    const float* noise         = (const float*)d_in[3];
    const float* weight        = (const float*)d_in[4];
    const float* bias          = (const float*)d_in[5];
    float* out = (float*)d_out;

    const int N = in_sizes[1];   // examples
    const int V = in_sizes[3];   // vocab size

    prep_kernel<<<1024, 256>>>(input, N, V);
    scatter_kernel<<<(N * NCOLS + 255) / 256, 256>>>(target, noise_samples, N);
    dot_kernel<<<DOT_BLOCKS, DOT_WARPS * 32>>>(weight, bias, noise, out, V, N);
}